// round 17
// baseline (speedup 1.0000x reference)
#include <cuda_runtime.h>
#include <cuda_fp16.h>
#include <math.h>
#include <stdint.h>

// Problem shape (fixed by the dataset)
#define BATCH   4
#define S_LEN   2048
#define DMODEL  1024
#define NHEAD   16
#define HD      64
#define MTOK    (BATCH * S_LEN)        // 8192 token rows

// ---------------------------------------------------------------------------
// Scratch (device globals: allocation-free)
// ---------------------------------------------------------------------------
__device__ __align__(16) __half g_x_h[(size_t)MTOK * DMODEL];          // x fp16
__device__ __align__(16) __half g_wqkv_h[(size_t)3 * DMODEL * DMODEL]; // w_qkv^T [N][K]
__device__ __align__(16) __half g_wproj_h[(size_t)DMODEL * DMODEL];    // w_proj^T [N][K]
__device__ __align__(16) __half g_qkv_h[(size_t)MTOK * 3 * DMODEL];    // fp16 qkv
__device__ __align__(16) __half g_attn_h[(size_t)MTOK * DMODEL];       // attn out fp16

// bit-reinterpret __half2 -> uint32
__device__ __forceinline__ uint32_t h2u(__half2 h) {
    union { __half2 h; uint32_t u; } c;
    c.h = h;
    return c.u;
}

__device__ __forceinline__ void mma_f16(float* c, const uint32_t* a,
                                        const uint32_t* b) {
    asm volatile(
        "mma.sync.aligned.m16n8k16.row.col.f32.f16.f16.f32 "
        "{%0,%1,%2,%3}, {%4,%5,%6,%7}, {%8,%9}, {%0,%1,%2,%3};"
        : "+f"(c[0]), "+f"(c[1]), "+f"(c[2]), "+f"(c[3])
        : "r"(a[0]), "r"(a[1]), "r"(a[2]), "r"(a[3]), "r"(b[0]), "r"(b[1]));
}

__device__ __forceinline__ void ldmatrix_x4(
    uint32_t& r0, uint32_t& r1, uint32_t& r2, uint32_t& r3, uint32_t addr) {
    asm volatile(
        "ldmatrix.sync.aligned.m8n8.x4.shared.b16 {%0,%1,%2,%3}, [%4];"
        : "=r"(r0), "=r"(r1), "=r"(r2), "=r"(r3) : "r"(addr));
}

__device__ __forceinline__ void ldmatrix_x4_trans(
    uint32_t& r0, uint32_t& r1, uint32_t& r2, uint32_t& r3, uint32_t addr) {
    asm volatile(
        "ldmatrix.sync.aligned.m8n8.x4.trans.shared.b16 {%0,%1,%2,%3}, [%4];"
        : "=r"(r0), "=r"(r1), "=r"(r2), "=r"(r3) : "r"(addr));
}

__device__ __forceinline__ uint32_t smem_u32(const void* p) {
    uint32_t a;
    asm("{ .reg .u64 t; cvta.to.shared.u64 t, %1; cvt.u32.u64 %0, t; }"
        : "=r"(a) : "l"(p));
    return a;
}
__device__ __forceinline__ void cp_async16(uint32_t dst, const void* src) {
    asm volatile("cp.async.cg.shared.global [%0], [%1], 16;"
                 :: "r"(dst), "l"(src));
}
#define CP_COMMIT()  asm volatile("cp.async.commit_group;" ::: "memory")
#define CP_WAIT1()   asm volatile("cp.async.wait_group 1;" ::: "memory")
#define CP_WAIT0()   asm volatile("cp.async.wait_group 0;" ::: "memory")

// ---------------------------------------------------------------------------
// fp16 tensor-core GEMM: C[M,N] = A[M,K](f16) @ Bt[N,K](f16)^T + bias[N]
// Block 128x128, BK=64, 256 threads, 8 warps (2m x 4n), warp tile 64x32.
// 2-stage cp.async pipeline (16 boundaries instead of 32), 2 CTAs/SM.
// ldmatrix fragments; row stride 36 words (8 rows x 4-bank stride -> clean).
// Output: fp32 to Cf (if Ch == nullptr) or fp16 to Ch.
// ---------------------------------------------------------------------------
#define GBM 128
#define GBN 128
#define GBK 64
#define KPW 36                        // 64 fp16 data + 8 pad = 36 words/row
#define A_TW (128 * KPW)              // 4608 words
#define B_TW (128 * KPW)              // 4608 words
#define STG_W (A_TW + B_TW)           // 9216 words
#define GEMM_SMEM_BYTES (2 * STG_W * 4)   // 73728 B

__global__ __launch_bounds__(256, 2) void f16_gemm_kernel(
    const __half* __restrict__ A, const __half* __restrict__ Bt,
    const float* __restrict__ bias, float* __restrict__ Cf,
    __half* __restrict__ Ch, int M, int N, int K)
{
    extern __shared__ uint32_t smw[];
    const uint32_t smb = smem_u32(smw);

    const int tid  = threadIdx.x;
    const int wid  = tid >> 5;
    const int lane = tid & 31;
    const int g = lane >> 2;
    const int q = lane & 3;
    const int r8 = lane & 7;
    const int g4 = lane >> 3;

    const int wm = (wid & 1) << 6;    // 0 or 64
    const int wn = (wid >> 1) << 5;   // 0,32,64,96

    const int bm = blockIdx.y * GBM;
    const int bn = blockIdx.x * GBN;
    const int NT = K / GBK;

    // cp.async: 128 rows x 128B per tensor = 1024 cp16; per thread 4 A + 4 B.
    // row = tid>>1, halves [(tid&1)*64, +64)
    const int c_row = tid >> 1;            // 0..127
    const int c_h   = (tid & 1) << 5;      // half offset 0 or 32
    const int c_w   = (tid & 1) << 4;      // word offset 0 or 16

    auto issue = [&](int s, int kt) {
        uint32_t sb = smb + (uint32_t)(s * STG_W) * 4;
        const __half* Ar = A + (size_t)(bm + c_row) * K + kt * GBK + c_h;
        uint32_t ad = sb + (uint32_t)(c_row * KPW + c_w) * 4;
        const __half* Br = Bt + (size_t)(bn + c_row) * K + kt * GBK + c_h;
        uint32_t bd = sb + (uint32_t)(A_TW + c_row * KPW + c_w) * 4;
        #pragma unroll
        for (int c = 0; c < 4; c++) {
            cp_async16(ad + (c << 4), Ar + (c << 3));
            cp_async16(bd + (c << 4), Br + (c << 3));
        }
    };

    float acc[4][4][4];
    #pragma unroll
    for (int mi = 0; mi < 4; mi++)
        #pragma unroll
        for (int ni = 0; ni < 4; ni++)
            #pragma unroll
            for (int r = 0; r < 4; r++) acc[mi][ni][r] = 0.0f;

    issue(0, 0); CP_COMMIT();

    for (int kt = 0; kt < NT; kt++) {
        __syncthreads();   // all warps done reading buffer (kt+1)&1 (prev use)
        if (kt + 1 < NT) { issue((kt + 1) & 1, kt + 1); CP_COMMIT(); CP_WAIT1(); }
        else             { CP_WAIT0(); }
        __syncthreads();   // buffer kt&1 ready & visible

        const uint32_t As_b = smb + (uint32_t)((kt & 1) * STG_W) * 4;
        const uint32_t Bs_b = As_b + (uint32_t)A_TW * 4;

        #pragma unroll
        for (int s16 = 0; s16 < 4; s16++) {
            const int s8 = s16 << 3;                 // k word offset
            uint32_t af[4][4], bf[4][2];

            // A fragments: per mi one ldmatrix.x4
            #pragma unroll
            for (int mi = 0; mi < 4; mi++) {
                int row = wm + (mi << 4) + ((g4 & 1) << 3) + r8;
                uint32_t addr = As_b
                    + (uint32_t)(row * KPW + s8) * 4 + ((g4 >> 1) << 4);
                ldmatrix_x4(af[mi][0], af[mi][1], af[mi][2], af[mi][3], addr);
            }
            // B fragments: 2 ldmatrix.x4 cover n-pairs (0,1) and (2,3)
            #pragma unroll
            for (int nj = 0; nj < 2; nj++) {
                int row = wn + (nj << 4) + ((g4 >> 1) << 3) + r8;
                uint32_t addr = Bs_b
                    + (uint32_t)(row * KPW + s8) * 4 + ((g4 & 1) << 4);
                ldmatrix_x4(bf[2 * nj][0], bf[2 * nj][1],
                            bf[2 * nj + 1][0], bf[2 * nj + 1][1], addr);
            }
            #pragma unroll
            for (int mi = 0; mi < 4; mi++)
                #pragma unroll
                for (int ni = 0; ni < 4; ni++)
                    mma_f16(acc[mi][ni], af[mi], bf[ni]);
        }
    }

    // epilogue: bias add in fp32, then fp32 or fp16 store
    #pragma unroll
    for (int mi = 0; mi < 4; mi++) {
        int m = bm + wm + (mi << 4) + g;
        #pragma unroll
        for (int ni = 0; ni < 4; ni++) {
            int n = bn + wn + (ni << 3) + (q << 1);
            float2 bb = *(const float2*)&bias[n];
            float v00 = acc[mi][ni][0] + bb.x;
            float v01 = acc[mi][ni][1] + bb.y;
            float v10 = acc[mi][ni][2] + bb.x;
            float v11 = acc[mi][ni][3] + bb.y;
            if (Ch) {
                *(__half2*)&Ch[(size_t)m * N + n]       = __floats2half2_rn(v00, v01);
                *(__half2*)&Ch[(size_t)(m + 8) * N + n] = __floats2half2_rn(v10, v11);
            } else {
                *(float2*)&Cf[(size_t)m * N + n]       = make_float2(v00, v01);
                *(float2*)&Cf[(size_t)(m + 8) * N + n] = make_float2(v10, v11);
            }
        }
    }
}

// ---------------------------------------------------------------------------
// Prepass kernels (unchanged)
// ---------------------------------------------------------------------------
__global__ void cvt_f16_kernel(const float4* __restrict__ src,
                               __half2* __restrict__ dst, int n4)
{
    int i = blockIdx.x * blockDim.x + threadIdx.x;
    if (i < n4) {
        float4 v = src[i];
        dst[i * 2]     = __floats2half2_rn(v.x, v.y);
        dst[i * 2 + 1] = __floats2half2_rn(v.z, v.w);
    }
}

__global__ void transpose_f16_kernel(const float* __restrict__ src,
                                     __half* __restrict__ dst, int K, int N)
{
    __shared__ __half t[32][33];
    const int n0 = blockIdx.x * 32, k0 = blockIdx.y * 32;
    const int tx = threadIdx.x, ty = threadIdx.y;
    #pragma unroll
    for (int i = ty; i < 32; i += 8)
        t[i][tx] = __float2half_rn(src[(size_t)(k0 + i) * N + n0 + tx]);
    __syncthreads();
    #pragma unroll
    for (int i = ty; i < 32; i += 8)
        dst[(size_t)(n0 + i) * K + k0 + tx] = t[tx][i];
}

// ---------------------------------------------------------------------------
// Flash attention, fp16 mma.sync m16n8k16, causal. (round-16 proven)
// 64-row q-tile, 4 warps. cp.async double-buffered K/V staging.
// smem: Qs[64][36], Kb[2][64][36], Vb[2][64][36], Ps[64][36] = 55296 B.
// ---------------------------------------------------------------------------
#define AS 36
#define TILE_W (64 * AS)
#define ATTN_SMEM_BYTES (6 * TILE_W * 4)

__global__ __launch_bounds__(128) void attn_mma_kernel()
{
    extern __shared__ uint32_t smu[];
    uint32_t* Qs = smu;                 // [64][36]
    uint32_t* Kb = Qs + TILE_W;         // [2][64][36]
    uint32_t* Vb = Kb + 2 * TILE_W;     // [2][64][36]
    uint32_t* Ps = Vb + 2 * TILE_W;     // [64][36]
    const uint32_t kb_sm = smem_u32(Kb);
    const uint32_t vb_sm = smem_u32(Vb);

    const int tid  = threadIdx.x;
    const int wid  = tid >> 5;
    const int lane = tid & 31;
    const int g = lane >> 2;
    const int q = lane & 3;
    const int l8 = lane & 7;
    const int lt = lane >> 3;

    const int qt = blockIdx.x;
    const int bh = blockIdx.y;
    const int b  = bh >> 4;
    const int h  = bh & (NHEAD - 1);

    const int q0 = qt * 64;
    const int qr = wid << 4;
    const float NEG = -1e30f;

    auto issue_kv = [&](int stage, int kt) {
        const int k0 = kt * 64;
        uint32_t kd = kb_sm + (uint32_t)(stage * TILE_W) * 4;
        uint32_t vd = vb_sm + (uint32_t)(stage * TILE_W) * 4;
        #pragma unroll
        for (int r = 0; r < 4; r++) {
            int idx = tid + (r << 7);          // 0..511
            int row = idx >> 3;                // 0..63
            int ch  = (idx & 7) << 3;          // half offset 0..56
            const __half* kg = g_qkv_h
                + (size_t)(b * S_LEN + k0 + row) * (3 * DMODEL)
                + DMODEL + h * HD + ch;
            uint32_t off = (uint32_t)(row * AS + (ch >> 1)) * 4;
            cp_async16(kd + off, kg);
            cp_async16(vd + off, kg + DMODEL);
        }
    };

    // stage Q (fp16 copy, once)
    for (int i = tid; i < 1024; i += 128) {
        int row = i >> 4, c4 = (i & 15) << 2;
        uint2 v = *(const uint2*)(g_qkv_h
            + (size_t)(b * S_LEN + q0 + row) * (3 * DMODEL) + h * HD + c4);
        *(uint2*)&Qs[row * AS + (c4 >> 1)] = v;
    }

    float O[8][4];
    #pragma unroll
    for (int ni = 0; ni < 8; ni++)
        #pragma unroll
        for (int r = 0; r < 4; r++) O[ni][r] = 0.0f;
    float mrow0 = NEG, mrow1 = NEG, lrow0 = 0.0f, lrow1 = 0.0f;

    issue_kv(0, 0); CP_COMMIT();

    for (int kt = 0; kt <= qt; kt++) {
        __syncthreads();
        if (kt < qt) { issue_kv((kt + 1) & 1, kt + 1); CP_COMMIT(); CP_WAIT1(); }
        else         { CP_WAIT0(); }
        __syncthreads();

        const uint32_t* Ks = Kb + (kt & 1) * TILE_W;
        const uint32_t  vsb = vb_sm + (uint32_t)((kt & 1) * TILE_W) * 4;

        // S = Q @ K^T
        float s[8][4];
        #pragma unroll
        for (int ni = 0; ni < 8; ni++)
            #pragma unroll
            for (int r = 0; r < 4; r++) s[ni][r] = 0.0f;

        #pragma unroll
        for (int ks = 0; ks < 4; ks++) {
            const int s8 = ks << 3;
            uint32_t a[4];
            const uint32_t* ar = Qs + (qr + g) * AS + s8 + q;
            a[0] = ar[0];
            a[1] = ar[8 * AS];
            a[2] = ar[4];
            a[3] = ar[8 * AS + 4];
            #pragma unroll
            for (int ni = 0; ni < 8; ni++) {
                const uint32_t* br = Ks + (ni * 8 + g) * AS + s8 + q;
                uint32_t bb[2] = { br[0], br[4] };
                mma_f16(s[ni], a, bb);
            }
        }

        // scale + causal mask (diagonal tile only)
        #pragma unroll
        for (int ni = 0; ni < 8; ni++)
            #pragma unroll
            for (int r = 0; r < 4; r++) s[ni][r] *= 0.125f;
        if (kt == qt) {
            int r0 = qr + g, r1 = qr + g + 8;
            #pragma unroll
            for (int ni = 0; ni < 8; ni++) {
                int c = ni * 8 + (q << 1);
                if (c > r0)     s[ni][0] = NEG;
                if (c + 1 > r0) s[ni][1] = NEG;
                if (c > r1)     s[ni][2] = NEG;
                if (c + 1 > r1) s[ni][3] = NEG;
            }
        }

        // online softmax
        float mx0 = NEG, mx1 = NEG;
        #pragma unroll
        for (int ni = 0; ni < 8; ni++) {
            mx0 = fmaxf(mx0, fmaxf(s[ni][0], s[ni][1]));
            mx1 = fmaxf(mx1, fmaxf(s[ni][2], s[ni][3]));
        }
        mx0 = fmaxf(mx0, __shfl_xor_sync(0xffffffffu, mx0, 1));
        mx0 = fmaxf(mx0, __shfl_xor_sync(0xffffffffu, mx0, 2));
        mx1 = fmaxf(mx1, __shfl_xor_sync(0xffffffffu, mx1, 1));
        mx1 = fmaxf(mx1, __shfl_xor_sync(0xffffffffu, mx1, 2));

        float mn0 = fmaxf(mrow0, mx0), mn1 = fmaxf(mrow1, mx1);
        float corr0 = __expf(mrow0 - mn0), corr1 = __expf(mrow1 - mn1);
        float sum0 = 0.0f, sum1 = 0.0f;
        #pragma unroll
        for (int ni = 0; ni < 8; ni++) {
            s[ni][0] = __expf(s[ni][0] - mn0);
            s[ni][1] = __expf(s[ni][1] - mn0);
            s[ni][2] = __expf(s[ni][2] - mn1);
            s[ni][3] = __expf(s[ni][3] - mn1);
            sum0 += s[ni][0] + s[ni][1];
            sum1 += s[ni][2] + s[ni][3];
        }
        sum0 += __shfl_xor_sync(0xffffffffu, sum0, 1);
        sum0 += __shfl_xor_sync(0xffffffffu, sum0, 2);
        sum1 += __shfl_xor_sync(0xffffffffu, sum1, 1);
        sum1 += __shfl_xor_sync(0xffffffffu, sum1, 2);
        lrow0 = lrow0 * corr0 + sum0;
        lrow1 = lrow1 * corr1 + sum1;
        mrow0 = mn0; mrow1 = mn1;
        #pragma unroll
        for (int ni = 0; ni < 8; ni++) {
            O[ni][0] *= corr0; O[ni][1] *= corr0;
            O[ni][2] *= corr1; O[ni][3] *= corr1;
        }

        // P -> smem fp16 (warp-private stripe)
        #pragma unroll
        for (int ni = 0; ni < 8; ni++) {
            Ps[(qr + g) * AS + ni * 4 + q] =
                h2u(__floats2half2_rn(s[ni][0], s[ni][1]));
            Ps[(qr + g + 8) * AS + ni * 4 + q] =
                h2u(__floats2half2_rn(s[ni][2], s[ni][3]));
        }
        __syncwarp();

        // O += P @ V
        #pragma unroll
        for (int ks = 0; ks < 4; ks++) {
            const int s8 = ks << 3;
            uint32_t a[4];
            const uint32_t* ar = Ps + (qr + g) * AS + s8 + q;
            a[0] = ar[0];
            a[1] = ar[8 * AS];
            a[2] = ar[4];
            a[3] = ar[8 * AS + 4];

            uint32_t vb0[8], vb1[8];
            #pragma unroll
            for (int m = 0; m < 4; m++) {
                uint32_t addr = vsb + (uint32_t)(
                    (((ks << 4) + ((lt & 1) << 3) + l8) * AS
                     + ((m << 1) + (lt >> 1)) * 4) * 4);
                ldmatrix_x4_trans(vb0[2 * m], vb1[2 * m],
                                  vb0[2 * m + 1], vb1[2 * m + 1], addr);
            }
            #pragma unroll
            for (int ni = 0; ni < 8; ni++) {
                uint32_t bb[2] = { vb0[ni], vb1[ni] };
                mma_f16(O[ni], a, bb);
            }
        }
    }

    // normalize + store fp16
    float inv0 = 1.0f / lrow0, inv1 = 1.0f / lrow1;
    int r0 = q0 + qr + g, r1 = r0 + 8;
    __half* d0 = g_attn_h + (size_t)(b * S_LEN + r0) * DMODEL + h * HD;
    __half* d1 = g_attn_h + (size_t)(b * S_LEN + r1) * DMODEL + h * HD;
    #pragma unroll
    for (int ni = 0; ni < 8; ni++) {
        int c = ni * 8 + (q << 1);
        *(__half2*)&d0[c] = __floats2half2_rn(O[ni][0] * inv0, O[ni][1] * inv0);
        *(__half2*)&d1[c] = __floats2half2_rn(O[ni][2] * inv1, O[ni][3] * inv1);
    }
}

// ---------------------------------------------------------------------------
// kernel_launch: x, w_qkv, b_qkv, w_proj, b_proj
// ---------------------------------------------------------------------------
extern "C" void kernel_launch(void* const* d_in, const int* in_sizes, int n_in,
                              void* d_out, int out_size)
{
    const float* x      = (const float*)d_in[0];
    const float* w_qkv  = (const float*)d_in[1];
    const float* b_qkv  = (const float*)d_in[2];
    const float* w_proj = (const float*)d_in[3];
    const float* b_proj = (const float*)d_in[4];
    float* out = (float*)d_out;

    void *x_h, *wqkv_h, *wproj_h, *qkv_h, *attn_h;
    cudaGetSymbolAddress(&x_h, g_x_h);
    cudaGetSymbolAddress(&wqkv_h, g_wqkv_h);
    cudaGetSymbolAddress(&wproj_h, g_wproj_h);
    cudaGetSymbolAddress(&qkv_h, g_qkv_h);
    cudaGetSymbolAddress(&attn_h, g_attn_h);

    cudaFuncSetAttribute(f16_gemm_kernel,
                         cudaFuncAttributeMaxDynamicSharedMemorySize,
                         GEMM_SMEM_BYTES);
    cudaFuncSetAttribute(attn_mma_kernel,
                         cudaFuncAttributeMaxDynamicSharedMemorySize,
                         ATTN_SMEM_BYTES);

    // 0) prepass: x -> fp16; weights transpose-convert to [N][K] fp16
    {
        int n4x = MTOK * DMODEL / 4;
        cvt_f16_kernel<<<(n4x + 255) / 256, 256>>>(
            (const float4*)x, (__half2*)x_h, n4x);
        dim3 tblk(32, 8);
        dim3 tg1(3 * DMODEL / 32, DMODEL / 32);
        transpose_f16_kernel<<<tg1, tblk>>>(w_qkv, (__half*)wqkv_h,
                                            DMODEL, 3 * DMODEL);
        dim3 tg2(DMODEL / 32, DMODEL / 32);
        transpose_f16_kernel<<<tg2, tblk>>>(w_proj, (__half*)wproj_h,
                                            DMODEL, DMODEL);
    }

    // 1) QKV projection (fp16 MMA, fp16 output)
    {
        dim3 grid(3 * DMODEL / GBN, MTOK / GBM);
        f16_gemm_kernel<<<grid, 256, GEMM_SMEM_BYTES>>>(
            (const __half*)x_h, (const __half*)wqkv_h, b_qkv,
            nullptr, (__half*)qkv_h, MTOK, 3 * DMODEL, DMODEL);
    }

    // 2) causal flash attention (fp16 MMA, cp.async double-buffered K/V)
    {
        dim3 grid(S_LEN / 64, BATCH * NHEAD);
        attn_mma_kernel<<<grid, 128, ATTN_SMEM_BYTES>>>();
    }

    // 3) output projection (fp16 MMA, fp32 output)
    {
        dim3 grid(DMODEL / GBN, MTOK / GBM);
        f16_gemm_kernel<<<grid, 256, GEMM_SMEM_BYTES>>>(
            (const __half*)attn_h, (const __half*)wproj_h, b_proj,
            out, nullptr, MTOK, DMODEL, DMODEL);
    }
}